// round 2
// baseline (speedup 1.0000x reference)
#include <cuda_runtime.h>
#include <cuda_bf16.h>
#include <cstdint>

// ---------------- problem constants ----------------
#define BATCH   16
#define NTOK    577
#define CDIM    1024
#define HEADS   16
#define HDIM    64
#define HIDDEN  4096
#define MROWS   (BATCH * NTOK)     // 9232
#define NPAD    640                // seq padded to 5*128
#define BH      (BATCH * HEADS)    // 256

// ---------------- scratch (device globals; no allocs allowed) ----------------
__device__ float g_h [MROWS * CDIM];    // LN1 out (tf32-rounded)
__device__ float g_q [MROWS * CDIM];
__device__ float g_k [MROWS * CDIM];
__device__ float g_v [MROWS * CDIM];
__device__ float g_S [(long)BH * NPAD * NPAD];  // scores, then P in-place
__device__ float g_Vt[(long)BH * HDIM * NPAD];  // V transposed per head, zero-padded
__device__ float g_o [MROWS * CDIM];    // attention out (packed)
__device__ float g_x1[MROWS * CDIM];    // x + proj (fp32 exact)
__device__ float g_h2[MROWS * CDIM];    // LN2 out
__device__ float g_m1[(long)MROWS * HIDDEN];
__device__ float g_Wq[CDIM * CDIM];
__device__ float g_Wk[CDIM * CDIM];
__device__ float g_Wv[CDIM * CDIM];
__device__ float g_Wp[CDIM * CDIM];
__device__ float g_W1[HIDDEN * CDIM];
__device__ float g_W2[CDIM * HIDDEN];

// ---------------- helpers ----------------
__device__ __forceinline__ float tf32r(float x) {
    asm("cvt.rna.tf32.f32 %0, %1;" : "=f"(x) : "f"(x));
    return x;
}

// round fp32 -> tf32-valued fp32
__global__ void cvt_kernel(const float* __restrict__ src, float* __restrict__ dst, int n) {
    int i = blockIdx.x * 256 + threadIdx.x;
    if (i < n) dst[i] = tf32r(src[i]);
}

// ---------------- LayerNorm (row = 1024) ----------------
__global__ __launch_bounds__(256) void ln_kernel(
    const float* __restrict__ x, const float* __restrict__ gw,
    const float* __restrict__ bw, float* __restrict__ out)
{
    long row = blockIdx.x;
    const float* xr = x + row * CDIM;
    float* orow = out + row * CDIM;
    int tid = threadIdx.x;
    float v[4]; float s = 0.f, sq = 0.f;
#pragma unroll
    for (int i = 0; i < 4; i++) { v[i] = xr[tid + 256 * i]; s += v[i]; sq += v[i] * v[i]; }
#pragma unroll
    for (int o = 16; o > 0; o >>= 1) {
        s  += __shfl_xor_sync(0xffffffffu, s,  o);
        sq += __shfl_xor_sync(0xffffffffu, sq, o);
    }
    __shared__ float ss[8], qq[8];
    int warp = tid >> 5, lane = tid & 31;
    if (lane == 0) { ss[warp] = s; qq[warp] = sq; }
    __syncthreads();
    float ts = 0.f, tq = 0.f;
#pragma unroll
    for (int i = 0; i < 8; i++) { ts += ss[i]; tq += qq[i]; }
    float mean = ts * (1.f / CDIM);
    float var  = tq * (1.f / CDIM) - mean * mean;
    float rsd  = rsqrtf(var + 1e-5f);
#pragma unroll
    for (int i = 0; i < 4; i++) {
        int c = tid + 256 * i;
        orow[c] = tf32r((v[i] - mean) * rsd * gw[c] + bw[c]);
    }
}

// ---------------- softmax (in-place on S rows; writes zero padding) ----------------
__global__ __launch_bounds__(256) void softmax_kernel(float* __restrict__ S) {
    int q = blockIdx.x;   // 0..576
    int z = blockIdx.y;   // 0..255
    float* row = S + (long)z * NPAD * NPAD + (long)q * NPAD;
    int tid = threadIdx.x;
    int warp = tid >> 5, lane = tid & 31;

    float v[3]; float mx = -1e30f;
#pragma unroll
    for (int i = 0; i < 3; i++) {
        int c = tid + 256 * i;
        v[i] = (c < NTOK) ? row[c] : -1e30f;
        mx = fmaxf(mx, v[i]);
    }
#pragma unroll
    for (int o = 16; o > 0; o >>= 1) mx = fmaxf(mx, __shfl_xor_sync(0xffffffffu, mx, o));
    __shared__ float red[8];
    if (lane == 0) red[warp] = mx;
    __syncthreads();
    float m2 = red[0];
#pragma unroll
    for (int i = 1; i < 8; i++) m2 = fmaxf(m2, red[i]);
    __syncthreads();

    float e[3]; float s = 0.f;
#pragma unroll
    for (int i = 0; i < 3; i++) {
        int c = tid + 256 * i;
        e[i] = (c < NTOK) ? __expf(v[i] - m2) : 0.f;
        s += e[i];
    }
#pragma unroll
    for (int o = 16; o > 0; o >>= 1) s += __shfl_xor_sync(0xffffffffu, s, o);
    if (lane == 0) red[warp] = s;
    __syncthreads();
    float tot = 0.f;
#pragma unroll
    for (int i = 0; i < 8; i++) tot += red[i];
    float inv = 1.f / tot;
#pragma unroll
    for (int i = 0; i < 3; i++) {
        int c = tid + 256 * i;
        if (c < NPAD) row[c] = (c < NTOK) ? tf32r(e[i] * inv) : 0.f;
    }
}

// ---------------- V transpose: v[(b*577+k)*1024 + h*64 + d] -> Vt[z][d][k(pad 640)] ----------------
__global__ __launch_bounds__(256) void vtrans_kernel(
    const float* __restrict__ v, float* __restrict__ Vt)
{
    int kb = blockIdx.x;           // 0..19 (k block of 32)
    int z  = blockIdx.y;           // bh
    int bb = z >> 4, hh = z & 15;
    __shared__ float tile[32][65];
    int tid = threadIdx.x;
#pragma unroll
    for (int e = 0; e < 8; e++) {
        int idx = tid + e * 256;
        int kk = idx >> 6, dd = idx & 63;
        int kg = kb * 32 + kk;
        tile[kk][dd] = (kg < NTOK)
            ? v[((long)(bb * NTOK + kg)) * CDIM + hh * HDIM + dd] : 0.f;
    }
    __syncthreads();
#pragma unroll
    for (int e = 0; e < 8; e++) {
        int idx = tid + e * 256;
        int dd = idx >> 5, kk = idx & 31;
        Vt[(long)z * HDIM * NPAD + (long)dd * NPAD + kb * 32 + kk] = tile[kk][dd];
    }
}

// ---------------- generic tf32 tensor-core GEMM ----------------
// C[m][n] = alpha * sum_k A[m][k] * B[n][k]  (+bias, +act, +res)
// MODE 0: dense, batch 1.  MODE 1: per-(b,h) QK^T -> S.  MODE 2: per-(b,h) P*V^T -> o (scattered).
#define BM 128
#define BN 128
#define BKT 16
#define LDS_ 20  // padded row stride (floats): conflict-free, 16B-aligned rows

template<int MODE, int ACT, bool TF32OUT, bool HAS_BIAS, bool HAS_RES>
__global__ __launch_bounds__(256) void gemm_tf32(
    const float* __restrict__ A, int lda,
    const float* __restrict__ Bw, int ldb,
    float* __restrict__ Cout, int ldc,
    const float* __restrict__ bias,
    const float* __restrict__ res,
    int M, int Nn, int K, float alpha)
{
    __shared__ float sA[2][BM * LDS_];
    __shared__ float sB[2][BN * LDS_];

    int tid  = threadIdx.x;
    int lane = tid & 31;
    int warp = tid >> 5;
    int wm = (warp >> 2) * 64;    // 0 / 64
    int wn = (warp & 3) * 32;     // 0..96

    long aOff = 0, bOff = 0, cOff = 0;
    if (MODE == 1) {
        int bb = blockIdx.z >> 4, hh = blockIdx.z & 15;
        aOff = ((long)bb * NTOK) * lda + hh * HDIM;
        bOff = ((long)bb * NTOK) * ldb + hh * HDIM;
        cOff = (long)blockIdx.z * NPAD * NPAD;
    } else if (MODE == 2) {
        int bb = blockIdx.z >> 4, hh = blockIdx.z & 15;
        aOff = (long)blockIdx.z * NPAD * NPAD;
        bOff = (long)blockIdx.z * HDIM * NPAD;
        cOff = ((long)bb * NTOK) * ldc + hh * HDIM;
    }
    const float* Ab = A  + aOff;
    const float* Bb = Bw + bOff;

    int mBase = blockIdx.y * BM;
    int nBase = blockIdx.x * BN;

    float acc[4][4][4];
#pragma unroll
    for (int i = 0; i < 4; i++)
#pragma unroll
        for (int j = 0; j < 4; j++)
#pragma unroll
            for (int l = 0; l < 4; l++) acc[i][j][l] = 0.f;

    // per-thread load coordinates: 2 float4 vectors per operand per tile
    const int r0v = tid >> 2;             // 0..63
    const int r1v = r0v + 64;             // 64..127
    const int c4  = (tid & 3) * 4;        // 0,4,8,12
    const int gr0 = mBase + r0v, gr1 = mBase + r1v;
    const int gn0 = nBase + r0v, gn1 = nBase + r1v;
    const bool am0 = gr0 < M, am1 = gr1 < M;
    const bool bm0 = gn0 < Nn, bm1 = gn1 < Nn;
    const float4 z4 = make_float4(0.f, 0.f, 0.f, 0.f);

    int KT = K / BKT;
    float4 ra0, ra1, rb0, rb1;

    // prologue: tile 0
    ra0 = am0 ? *(const float4*)(Ab + (long)gr0 * lda + c4) : z4;
    ra1 = am1 ? *(const float4*)(Ab + (long)gr1 * lda + c4) : z4;
    rb0 = bm0 ? *(const float4*)(Bb + (long)gn0 * ldb + c4) : z4;
    rb1 = bm1 ? *(const float4*)(Bb + (long)gn1 * ldb + c4) : z4;
    *(float4*)&sA[0][r0v * LDS_ + c4] = ra0;
    *(float4*)&sA[0][r1v * LDS_ + c4] = ra1;
    *(float4*)&sB[0][r0v * LDS_ + c4] = rb0;
    *(float4*)&sB[0][r1v * LDS_ + c4] = rb1;
    __syncthreads();

    int cur = 0;
    const int ar = lane >> 2;  // 0..7
    const int ac = lane & 3;   // 0..3

    for (int kt = 0; kt < KT; kt++) {
        bool more = (kt + 1 < KT);
        if (more) {
            int ko = (kt + 1) * BKT + c4;
            ra0 = am0 ? *(const float4*)(Ab + (long)gr0 * lda + ko) : z4;
            ra1 = am1 ? *(const float4*)(Ab + (long)gr1 * lda + ko) : z4;
            rb0 = bm0 ? *(const float4*)(Bb + (long)gn0 * ldb + ko) : z4;
            rb1 = bm1 ? *(const float4*)(Bb + (long)gn1 * ldb + ko) : z4;
        }
#pragma unroll
        for (int ks = 0; ks < BKT; ks += 8) {
            uint32_t af[4][4], bf[4][2];
#pragma unroll
            for (int fm = 0; fm < 4; fm++) {
                int r = wm + fm * 16 + ar;
                af[fm][0] = __float_as_uint(sA[cur][(r    ) * LDS_ + ks + ac    ]);
                af[fm][1] = __float_as_uint(sA[cur][(r + 8) * LDS_ + ks + ac    ]);
                af[fm][2] = __float_as_uint(sA[cur][(r    ) * LDS_ + ks + ac + 4]);
                af[fm][3] = __float_as_uint(sA[cur][(r + 8) * LDS_ + ks + ac + 4]);
            }
#pragma unroll
            for (int fn = 0; fn < 4; fn++) {
                int n = wn + fn * 8 + ar;
                bf[fn][0] = __float_as_uint(sB[cur][n * LDS_ + ks + ac    ]);
                bf[fn][1] = __float_as_uint(sB[cur][n * LDS_ + ks + ac + 4]);
            }
#pragma unroll
            for (int fm = 0; fm < 4; fm++)
#pragma unroll
                for (int fn = 0; fn < 4; fn++) {
                    float* c = acc[fm][fn];
                    asm volatile(
                        "mma.sync.aligned.m16n8k8.row.col.f32.tf32.tf32.f32 "
                        "{%0,%1,%2,%3},{%4,%5,%6,%7},{%8,%9},{%0,%1,%2,%3};\n"
                        : "+f"(c[0]), "+f"(c[1]), "+f"(c[2]), "+f"(c[3])
                        : "r"(af[fm][0]), "r"(af[fm][1]), "r"(af[fm][2]), "r"(af[fm][3]),
                          "r"(bf[fn][0]), "r"(bf[fn][1]));
                }
        }
        if (more) {
            int nxt = cur ^ 1;
            *(float4*)&sA[nxt][r0v * LDS_ + c4] = ra0;
            *(float4*)&sA[nxt][r1v * LDS_ + c4] = ra1;
            *(float4*)&sB[nxt][r0v * LDS_ + c4] = rb0;
            *(float4*)&sB[nxt][r1v * LDS_ + c4] = rb1;
            __syncthreads();
            cur = nxt;
        }
    }

    // epilogue
#pragma unroll
    for (int fm = 0; fm < 4; fm++) {
        int rr0 = mBase + wm + fm * 16 + ar;
#pragma unroll
        for (int fn = 0; fn < 4; fn++) {
            int cc0 = nBase + wn + fn * 8 + ac * 2;
            float* c = acc[fm][fn];
#pragma unroll
            for (int i = 0; i < 4; i++) {
                int rr = rr0 + ((i & 2) ? 8 : 0);
                int nc = cc0 + (i & 1);
                if (rr < M && nc < Nn) {
                    float vv = c[i] * alpha;
                    if (HAS_BIAS) vv += bias[nc];
                    if (ACT == 1) vv = vv / (1.f + __expf(-1.702f * vv));  // fast_gelu
                    if (HAS_RES)  vv += res[(long)rr * ldc + nc];
                    if (TF32OUT)  vv = tf32r(vv);
                    Cout[cOff + (long)rr * ldc + nc] = vv;
                }
            }
        }
    }
}

// ---------------- host launcher ----------------
static inline float* sym(const void* s) {
    void* p = nullptr;
    cudaGetSymbolAddress(&p, s);
    return (float*)p;
}

extern "C" void kernel_launch(void* const* d_in, const int* in_sizes, int n_in,
                              void* d_out, int out_size)
{
    const float* x   = (const float*)d_in[0];
    const float* n1g = (const float*)d_in[1];
    const float* n1b = (const float*)d_in[2];
    const float* Wq  = (const float*)d_in[3];
    const float* Wk  = (const float*)d_in[4];
    const float* Wv  = (const float*)d_in[5];
    const float* Wp  = (const float*)d_in[6];
    const float* bp  = (const float*)d_in[7];
    const float* n2g = (const float*)d_in[8];
    const float* n2b = (const float*)d_in[9];
    const float* W1  = (const float*)d_in[10];
    const float* b1  = (const float*)d_in[11];
    const float* W2  = (const float*)d_in[12];
    const float* b2  = (const float*)d_in[13];
    float* out = (float*)d_out;

    float* ph  = sym(g_h);   float* pq  = sym(g_q);   float* pk  = sym(g_k);
    float* pv  = sym(g_v);   float* pS  = sym(g_S);   float* pVt = sym(g_Vt);
    float* po  = sym(g_o);   float* px1 = sym(g_x1);  float* ph2 = sym(g_h2);
    float* pm1 = sym(g_m1);
    float* pWq = sym(g_Wq);  float* pWk = sym(g_Wk);  float* pWv = sym(g_Wv);
    float* pWp = sym(g_Wp);  float* pW1 = sym(g_W1);  float* pW2 = sym(g_W2);

    const int CC = CDIM * CDIM;           // 1M
    const int WH = HIDDEN * CDIM;         // 4M
    cvt_kernel<<<(CC + 255) / 256, 256>>>(Wq, pWq, CC);
    cvt_kernel<<<(CC + 255) / 256, 256>>>(Wk, pWk, CC);
    cvt_kernel<<<(CC + 255) / 256, 256>>>(Wv, pWv, CC);
    cvt_kernel<<<(CC + 255) / 256, 256>>>(Wp, pWp, CC);
    cvt_kernel<<<(WH + 255) / 256, 256>>>(W1, pW1, WH);
    cvt_kernel<<<(WH + 255) / 256, 256>>>(W2, pW2, WH);

    // LN1
    ln_kernel<<<MROWS, 256>>>(x, n1g, n1b, ph);

    // QKV projections (no bias)
    dim3 gQKV(CDIM / BN, (MROWS + BM - 1) / BM, 1);
    gemm_tf32<0, 0, true, false, false><<<gQKV, 256>>>(
        ph, CDIM, pWq, CDIM, pq, CDIM, nullptr, nullptr, MROWS, CDIM, CDIM, 1.f);
    gemm_tf32<0, 0, true, false, false><<<gQKV, 256>>>(
        ph, CDIM, pWk, CDIM, pk, CDIM, nullptr, nullptr, MROWS, CDIM, CDIM, 1.f);
    gemm_tf32<0, 0, true, false, false><<<gQKV, 256>>>(
        ph, CDIM, pWv, CDIM, pv, CDIM, nullptr, nullptr, MROWS, CDIM, CDIM, 1.f);

    // V transpose (zero-padded k)
    vtrans_kernel<<<dim3(NPAD / 32, BH, 1), 256>>>(pv, pVt);

    // S = scale * Q K^T   (scale = 64^-0.5 = 0.125)
    dim3 gQK(NPAD / BN, NPAD / BM, BH);  // 5 x 5 x 256
    gemm_tf32<1, 0, false, false, false><<<gQK, 256>>>(
        pq, CDIM, pk, CDIM, pS, NPAD, nullptr, nullptr, NTOK, NTOK, HDIM, 0.125f);

    // softmax rows (in place, writes zero padding)
    softmax_kernel<<<dim3(NTOK, BH, 1), 256>>>(pS);

    // O = P V^T  -> scattered back to packed [row, h*64+d]
    dim3 gPV(1, NPAD / BM, BH);          // 1 x 5 x 256
    gemm_tf32<2, 0, true, false, false><<<gPV, 256>>>(
        pS, NPAD, pVt, NPAD, po, CDIM, nullptr, nullptr, NTOK, HDIM, NPAD, 1.f);

    // x1 = x + O Wp^T + bp
    gemm_tf32<0, 0, false, true, true><<<gQKV, 256>>>(
        po, CDIM, pWp, CDIM, px1, CDIM, bp, x, MROWS, CDIM, CDIM, 1.f);

    // LN2
    ln_kernel<<<MROWS, 256>>>(px1, n2g, n2b, ph2);

    // m1 = fast_gelu(h2 W1^T + b1)
    dim3 gFC1(HIDDEN / BN, (MROWS + BM - 1) / BM, 1);
    gemm_tf32<0, 1, true, true, false><<<gFC1, 256>>>(
        ph2, CDIM, pW1, CDIM, pm1, HIDDEN, b1, nullptr, MROWS, HIDDEN, CDIM, 1.f);

    // out = x1 + m1 W2^T + b2
    dim3 gFC2(CDIM / BN, (MROWS + BM - 1) / BM, 1);
    gemm_tf32<0, 0, false, true, true><<<gFC2, 256>>>(
        pm1, HIDDEN, pW2, HIDDEN, out, CDIM, b2, px1, MROWS, CDIM, HIDDEN, 1.f);
}